// round 12
// baseline (speedup 1.0000x reference)
#include <cuda_runtime.h>
#include <cstdint>

// ConvTranspose2d(64->64,k4,s2,p1)+bias+mish+(+0.5,clip,*2) via mma.sync fp16 (f32 accum).
// y[p,oc] = sum_k A[p,k]*B[oc,k], k = (b*2+a)*64 + ic, K=256.
// Tile = 4 output rows per parity: oh = ph + 8T + 2*ohi (ohi 0..3), ow = 2m+pw.
//   Rb = 4T + ph ; input rows Rb-1..Rb+3 ; A[p,k] = x[n,ic,Rb+ohi-a,m+pw-b] (0 OOB)
//   B[oc,k] = w[oc,ic,(1-ph)+2a,(1-pw)+2b]
// 9-slot fp16 row ring (slot=rg%9, row 128B = 64 ic, 16B-chunk swizzle ^(j&7)<<4,
// OOB j -> ZROW). Staging LDG.32 ic-pair -> cvt.rn.f16x2 -> STS.32.
// 512 thr, 16 warps = (pw, mo): warp tile 32px x 64oc (acc 64), LDSM:MMA = 0.375.
// Unit = 2 tiles (512 units/ph, 74 slots); phase-A stages tile1's 4 rows under tile0.
// Epilogue: 2x32KB ys double buffer, 4 chunks x 16oc, store(q) overlaps write(q+1).

#define NT 512
#define SM_B    256
#define SM_RING (SM_B + 65536)             // 65792
#define ZROW    576
#define SM_YS   (SM_RING + 577 * 128)      // 139648
#define SMEM_TOTAL (SM_YS + 65536)         // 205184

static __device__ __forceinline__ uint32_t s2u(const void* p) {
    uint32_t a;
    asm("{ .reg .u64 t; cvta.to.shared.u64 t, %1; cvt.u32.u64 %0, t; }" : "=r"(a) : "l"(p));
    return a;
}
static __device__ __forceinline__ uint32_t f2h2(float lo, float hi) {
    uint32_t r;
    asm("cvt.rn.f16x2.f32 %0, %1, %2;" : "=r"(r) : "f"(hi), "f"(lo));
    return r;
}
static __device__ __forceinline__ void sts32(uint32_t addr, uint32_t v) {
    asm volatile("st.shared.b32 [%0], %1;" :: "r"(addr), "r"(v) : "memory");
}
static __device__ __forceinline__ void ldsm4(uint32_t* r, uint32_t addr) {
    asm volatile("ldmatrix.sync.aligned.m8n8.x4.shared.b16 {%0,%1,%2,%3}, [%4];"
                 : "=r"(r[0]), "=r"(r[1]), "=r"(r[2]), "=r"(r[3]) : "r"(addr));
}
static __device__ __forceinline__ void mma16(float* d, const uint32_t* a,
                                             uint32_t b0, uint32_t b1) {
    asm volatile("mma.sync.aligned.m16n8k16.row.col.f32.f16.f16.f32 "
                 "{%0,%1,%2,%3}, {%4,%5,%6,%7}, {%8,%9}, {%0,%1,%2,%3};"
                 : "+f"(d[0]), "+f"(d[1]), "+f"(d[2]), "+f"(d[3])
                 : "r"(a[0]), "r"(a[1]), "r"(a[2]), "r"(a[3]), "r"(b0), "r"(b1));
}
__device__ __forceinline__ float postop(float y) {
    // mish(y) = y*(t^2+2t)/(t^2+2t+2), t=e^y ; then +0.5, clip[-1,1], *2
    float t = __expf(fminf(y, 30.0f));
    float u = t * (t + 2.0f);
    float mish = y * __fdividef(u, u + 2.0f);
    float v = fminf(fmaxf(mish + 0.5f, -1.0f), 1.0f);
    return v * 2.0f;
}
// ys: 32 rows x 1024B (256 px), 16B-chunk XOR swizzle by row
static __device__ __forceinline__ uint32_t ysaddr(uint32_t base, int row, int p) {
    return base + (uint32_t)row * 1024 + ((((uint32_t)p >> 2) ^ (uint32_t)(row & 63)) << 4)
         + (((uint32_t)p & 3) << 2);
}

// stage nrows rows starting at rg0: LDG.32 ic-pair -> f16x2 -> STS.32 ; slot = rg%9
static __device__ __forceinline__ void stage_rows(const float* xn, int rg0, int nrows,
                                                  uint32_t sb, int tid) {
    const int total = nrows * 2048;        // 32 icp x 64 j per row
#pragma unroll 4
    for (int idx = tid; idx < total; idx += NT) {
        int j   = idx & 63;
        int icp = (idx >> 6) & 31;
        int rr  = idx >> 11;
        int rg  = rg0 + rr;
        float v0 = 0.0f, v1 = 0.0f;
        if ((unsigned)rg < 64u) {
            const float* p0 = xn + ((2 * icp) * 64 + rg) * 64 + j;
            v0 = __ldg(p0);
            v1 = __ldg(p0 + 4096);
        }
        int row = ((rg + 9) % 9) * 64 + j;
        uint32_t dst = sb + SM_RING + row * 128
                     + (((uint32_t)icp << 2) ^ (((uint32_t)j & 7) << 4));
        sts32(dst, f2h2(v0, v1));
    }
}

__global__ __launch_bounds__(NT, 1)
void convt_mma_kernel(const float* __restrict__ x,
                      const float* __restrict__ weight,
                      const float* __restrict__ bias,
                      float* __restrict__ out) {
    extern __shared__ char smem[];
    const uint32_t sb = s2u(smem);
    const int tid  = threadIdx.x;
    const int warp = tid >> 5;
    const int lane = tid & 31;
    const int ph   = blockIdx.x & 1;
    const int slot = blockIdx.x >> 1;      // 0..73

    if (tid < 64) ((float*)smem)[tid] = bias[tid];

    // ---- stage B once (fp16): row = pw*64+oc (512B), word kp: byte = kp*4 ^ ((oc&7)<<4) ----
    for (int it = 0; it < 32; it++) {
        int idx = tid + it * NT;           // 0..16383 (k-pairs)
        int kp = idx & 127;                // k0 = 2*kp
        int oc = (idx >> 7) & 63;
        int pw = idx >> 13;
        int k0 = 2 * kp;
        int g = k0 >> 6, ic = k0 & 63, a = g & 1, b = g >> 1;
        int kh = (1 - ph) + 2 * a;
        int kw = (1 - pw) + 2 * b;
        const float* wp = weight + ((oc * 64 + ic) << 4) + (kh << 2) + kw;
        float f0 = __ldg(wp);
        float f1 = __ldg(wp + 16);         // ic+1, same (kh,kw)
        uint32_t byte = ((uint32_t)(kp << 2)) ^ ((uint32_t)(oc & 7) << 4);
        sts32(sb + SM_B + (pw * 64 + oc) * 512 + byte, f2h2(f0, f1));
    }
    if (tid < 32) sts32(sb + SM_RING + ZROW * 128 + tid * 4, 0u);   // zero row

    // warp roles: pw | mo
    const int pw = warp >> 3;
    const int mo = warp & 7;
    const int p0 = 32 * mo;                // p = ohi*64 + m
    const int ohi = mo >> 1;               // 0..3
    const int msub0 = 32 * (mo & 1);

    const int l15 = lane & 15;
    const int lhi = lane >> 4;
    const int oc_l = (lane & 7) + 8 * lhi;
    const uint32_t khalf = (uint32_t)((lane >> 3) & 1) << 4;
    const uint32_t swzB  = (uint32_t)(lane & 7) << 4;
    uint32_t rbB[4];
#pragma unroll
    for (int jp = 0; jp < 4; jp++)
        rbB[jp] = sb + SM_B + (uint32_t)(pw * 64 + 16 * jp + oc_l) * 512;

    const int gL = lane >> 2, tg = lane & 3;
    const float* bsm = (const float*)smem;

    for (int u = slot; u < 512; u += 74) {
        const int n  = u >> 3;
        const int Tp = u & 7;
        const int Rb0 = 8 * Tp + ph;
        const float* xn = x + (size_t)n * (64 * 64 * 64);

        // ---- prologue: rows Rb0-1..Rb0+3 ----
        stage_rows(xn, Rb0 - 1, 5, sb, tid);
        __syncthreads();

        for (int tl = 0; tl < 2; tl++) {
            const int Rb = Rb0 + 4 * tl;
            const int T  = 2 * Tp + tl;

            // ---- phase A: stage tile1's rows Rb0+4..Rb0+7 during tile0 ----
            if (tl == 0) stage_rows(xn, Rb0 + 4, 4, sb, tid);

            // ---- phase B: mma, 16 k16-steps, warp tile 32px x 64oc ----
            float acc[2][8][4];
#pragma unroll
            for (int i = 0; i < 2; i++)
#pragma unroll
                for (int j = 0; j < 8; j++)
#pragma unroll
                    for (int e = 0; e < 4; e++) acc[i][j][e] = 0.0f;

#pragma unroll
            for (int g = 0; g < 4; g++) {
                const int a = g & 1, b = g >> 1;
                const int rgA = Rb + ohi - a;                    // Rb-1..Rb+3
                const int slotA = (rgA + 9) % 9;
                const int jA = msub0 + pw - b + l15;
                const int rowL0 = ((unsigned)jA < 64u) ? slotA * 64 + jA : ZROW;
                const int rowL1 = ((unsigned)(jA + 16) < 64u) ? slotA * 64 + jA + 16 : ZROW;
                const uint32_t base0 = sb + SM_RING + (uint32_t)rowL0 * 128;
                const uint32_t base1 = sb + SM_RING + (uint32_t)rowL1 * 128;
                const uint32_t r0 = (uint32_t)(rowL0 & 7);
                const uint32_t r1 = (uint32_t)(rowL1 & 7);
                const uint32_t kbg = (uint32_t)g << 7;

#pragma unroll
                for (int s = 0; s < 4; s++) {
                    const uint32_t ch = (uint32_t)(s << 1) + (uint32_t)lhi;
                    uint32_t Af0[4], Af1[4];
                    ldsm4(Af0, base0 + ((ch ^ r0) << 4));
                    ldsm4(Af1, base1 + ((ch ^ r1) << 4));
                    const uint32_t kb = (kbg + ((uint32_t)s << 5) + khalf) ^ swzB;
                    {
                        uint32_t Bf0[4], Bf1[4];
                        ldsm4(Bf0, rbB[0] + kb);
                        ldsm4(Bf1, rbB[1] + kb);
                        mma16(acc[0][0], Af0, Bf0[0], Bf0[1]);
                        mma16(acc[0][1], Af0, Bf0[2], Bf0[3]);
                        mma16(acc[0][2], Af0, Bf1[0], Bf1[1]);
                        mma16(acc[0][3], Af0, Bf1[2], Bf1[3]);
                        mma16(acc[1][0], Af1, Bf0[0], Bf0[1]);
                        mma16(acc[1][1], Af1, Bf0[2], Bf0[3]);
                        mma16(acc[1][2], Af1, Bf1[0], Bf1[1]);
                        mma16(acc[1][3], Af1, Bf1[2], Bf1[3]);
                    }
                    {
                        uint32_t Bf2[4], Bf3[4];
                        ldsm4(Bf2, rbB[2] + kb);
                        ldsm4(Bf3, rbB[3] + kb);
                        mma16(acc[0][4], Af0, Bf2[0], Bf2[1]);
                        mma16(acc[0][5], Af0, Bf2[2], Bf2[3]);
                        mma16(acc[0][6], Af0, Bf3[0], Bf3[1]);
                        mma16(acc[0][7], Af0, Bf3[2], Bf3[3]);
                        mma16(acc[1][4], Af1, Bf2[0], Bf2[1]);
                        mma16(acc[1][5], Af1, Bf2[2], Bf2[3]);
                        mma16(acc[1][6], Af1, Bf3[0], Bf3[1]);
                        mma16(acc[1][7], Af1, Bf3[2], Bf3[3]);
                    }
                }
            }
            __syncthreads();   // ring reads done; phase-A STS visible next tile

            // ---- phase C: ys 2x32KB double buffer, 4 chunks x 16oc (x 2pw x 256px) ----
            const uint32_t ysA = sb + SM_YS;
            const uint32_t ysB = sb + SM_YS + 32768;

#define WRITE_CHUNK(q, base) do {                                            \
    _Pragma("unroll")                                                        \
    for (int j2_ = 0; j2_ < 2; j2_++) {                                      \
        const int j_  = 2 * (q) + j2_;                                       \
        const int oc_ = 8 * j_ + 2 * tg;                                     \
        const int row_ = pw * 16 + 8 * j2_ + 2 * tg;                         \
        const float b0v_ = bsm[oc_], b1v_ = bsm[oc_ + 1];                    \
        _Pragma("unroll")                                                    \
        for (int i_ = 0; i_ < 2; i_++) {                                     \
            const int pr_ = p0 + 16 * i_ + gL;                               \
            sts32(ysaddr((base), row_,     pr_),     __float_as_uint(postop(acc[i_][j_][0] + b0v_))); \
            sts32(ysaddr((base), row_ + 1, pr_),     __float_as_uint(postop(acc[i_][j_][1] + b1v_))); \
            sts32(ysaddr((base), row_,     pr_ + 8), __float_as_uint(postop(acc[i_][j_][2] + b0v_))); \
            sts32(ysaddr((base), row_ + 1, pr_ + 8), __float_as_uint(postop(acc[i_][j_][3] + b1v_))); \
        }                                                                    \
    } } while (0)

#define STORE_CHUNK(q, base) do {                                            \
    const char* yb_ = smem + ((base) - sb);                                  \
    _Pragma("unroll")                                                        \
    for (int it_ = 0; it_ < 4; it_++) {                                      \
        int vid_ = tid + it_ * NT;                                           \
        int ow4_ = vid_ & 31;                                                \
        int rw_  = vid_ >> 5;          /* 0..63 */                           \
        int oh2_ = rw_ & 3;                                                  \
        int ocx_ = rw_ >> 2;           /* 0..15 */                           \
        int oc_  = 16 * (q) + ocx_;                                          \
        int p_   = oh2_ * 64 + 2 * ow4_;                                     \
        float4 v_;                                                           \
        v_.x = *(const float*)(yb_ + (ysaddr(0u, ocx_,      p_)));           \
        v_.y = *(const float*)(yb_ + (ysaddr(0u, 16 + ocx_, p_)));           \
        v_.z = *(const float*)(yb_ + (ysaddr(0u, ocx_,      p_ + 1)));       \
        v_.w = *(const float*)(yb_ + (ysaddr(0u, 16 + ocx_, p_ + 1)));       \
        int oh_ = ph + 8 * T + 2 * oh2_;                                     \
        *(float4*)(out + (((size_t)n * 64 + oc_) * 128 + oh_) * 128 + 4 * ow4_) = v_; \
    } } while (0)

            WRITE_CHUNK(0, ysA);
            __syncthreads();
            STORE_CHUNK(0, ysA); WRITE_CHUNK(1, ysB);
            __syncthreads();
            STORE_CHUNK(1, ysB); WRITE_CHUNK(2, ysA);
            __syncthreads();
            STORE_CHUNK(2, ysA); WRITE_CHUNK(3, ysB);
            __syncthreads();
            STORE_CHUNK(3, ysB);
            __syncthreads();
#undef WRITE_CHUNK
#undef STORE_CHUNK
        }
    }
}

extern "C" void kernel_launch(void* const* d_in, const int* in_sizes, int n_in,
                              void* d_out, int out_size) {
    const float* x      = (const float*)d_in[0];
    const float* weight = (const float*)d_in[1];
    const float* bias   = (const float*)d_in[2];
    float* out          = (float*)d_out;

    cudaFuncSetAttribute(convt_mma_kernel,
                         cudaFuncAttributeMaxDynamicSharedMemorySize, SMEM_TOTAL);
    convt_mma_kernel<<<148, NT, SMEM_TOTAL>>>(x, weight, bias, out);
}

// round 13
// speedup vs baseline: 1.0544x; 1.0544x over previous
#include <cuda_runtime.h>
#include <cstdint>

// ConvTranspose2d(64->64,k4,s2,p1)+bias+mish+(+0.5,clip,*2) via mma.sync fp16 (f32 accum).
// y[p,oc] = sum_k A[p,k]*B[oc,k], k = (b*2+a)*64 + ic, K=256.
//   pixel p=(ohi,m): oh = ph+4*tglob+2*ohi, ow = 2m+pw ; Rb = 2*tglob+ph
//   A[p,k] = x[n, ic, Rb+ohi-a, m+pw-b]  (zero OOB), B[oc,k]=w[oc,ic,(1-ph)+2a,(1-pw)+2b]
// Round-11 structure (best: 192.5us) + fixes:
//  - epilogue 2 chunks of 32oc (ys 2x32KB), 3 barriers/tile (was 6; final sync removed
//    -- next tile's sync1/sync2 already order all cross-warp hazards)
//  - staging: float2 LDG.64 + lane map (icp_lo,jp_lo) -> conflict-free STS banks
//    (was 4-way conflicted) and 8-sector LDG groups
// 5-slot fp16 row ring (row=slot*64+j, 128B = 64 ic, 16B-chunk swizzle ^(j&7)<<4,
// OOB j -> ZROW). 512 thr, 16 warps = (pw, och, mq), warp tile 32px x 32oc.
// Unit = 4 tiles (512 units/ph, 74 slots). Grid 148.

#define NT 512
#define SM_B    256
#define SM_RING (SM_B + 65536)             // 65792
#define ZROW    320
#define SM_YS   (SM_RING + 321 * 128)      // 106880
#define SMEM_TOTAL (SM_YS + 65536)         // 172416

static __device__ __forceinline__ uint32_t s2u(const void* p) {
    uint32_t a;
    asm("{ .reg .u64 t; cvta.to.shared.u64 t, %1; cvt.u32.u64 %0, t; }" : "=r"(a) : "l"(p));
    return a;
}
static __device__ __forceinline__ uint32_t f2h2(float lo, float hi) {
    uint32_t r;
    asm("cvt.rn.f16x2.f32 %0, %1, %2;" : "=r"(r) : "f"(hi), "f"(lo));
    return r;
}
static __device__ __forceinline__ void sts32(uint32_t addr, uint32_t v) {
    asm volatile("st.shared.b32 [%0], %1;" :: "r"(addr), "r"(v) : "memory");
}
static __device__ __forceinline__ void ldsm4(uint32_t* r, uint32_t addr) {
    asm volatile("ldmatrix.sync.aligned.m8n8.x4.shared.b16 {%0,%1,%2,%3}, [%4];"
                 : "=r"(r[0]), "=r"(r[1]), "=r"(r[2]), "=r"(r[3]) : "r"(addr));
}
static __device__ __forceinline__ void mma16(float* d, const uint32_t* a,
                                             uint32_t b0, uint32_t b1) {
    asm volatile("mma.sync.aligned.m16n8k16.row.col.f32.f16.f16.f32 "
                 "{%0,%1,%2,%3}, {%4,%5,%6,%7}, {%8,%9}, {%0,%1,%2,%3};"
                 : "+f"(d[0]), "+f"(d[1]), "+f"(d[2]), "+f"(d[3])
                 : "r"(a[0]), "r"(a[1]), "r"(a[2]), "r"(a[3]), "r"(b0), "r"(b1));
}
__device__ __forceinline__ float postop(float y) {
    // mish(y) = y*(t^2+2t)/(t^2+2t+2), t=e^y ; then +0.5, clip[-1,1], *2
    float t = __expf(fminf(y, 30.0f));
    float u = t * (t + 2.0f);
    float mish = y * __fdividef(u, u + 2.0f);
    float v = fminf(fmaxf(mish + 0.5f, -1.0f), 1.0f);
    return v * 2.0f;
}
// ys: 64 rows (pw*32 + ocy) x 512B (128 px), 16B-chunk XOR swizzle by (row&31)
static __device__ __forceinline__ uint32_t ysaddr(uint32_t base, int row, int p) {
    return base + (uint32_t)row * 512 + ((((uint32_t)p >> 2) ^ (uint32_t)(row & 31)) << 4)
         + (((uint32_t)p & 3) << 2);
}

// stage nrows rows from rg0: LDG.64 (float2, ic pair x j pair) -> 2x f16x2 STS.32
// lane map: idx bits [0:2)=jp_lo [2:5)=icp_lo [5:8)=jp_hi [8:10)=icp_hi [10:)=rr
// -> STS bank = icp ^ ((j&7)<<2): conflict-free; LDG groups 8 aligned 32B sectors.
static __device__ __forceinline__ void stage_rows(const float* xn, int rg0, int nrows,
                                                  uint32_t sb, int tid) {
    const int total = nrows * 1024;
#pragma unroll 4
    for (int idx = tid; idx < total; idx += NT) {
        int jp  = (idx & 3) | (((idx >> 5) & 7) << 2);    // 0..31
        int icp = ((idx >> 2) & 7) | (((idx >> 8) & 3) << 3);  // 0..31
        int rr  = idx >> 10;
        int rg  = rg0 + rr;
        int j0  = 2 * jp;
        float2 a0 = make_float2(0.0f, 0.0f), a1 = make_float2(0.0f, 0.0f);
        if ((unsigned)rg < 64u) {
            const float* p0 = xn + ((2 * icp) * 64 + rg) * 64 + j0;
            a0 = *(const float2*)p0;
            a1 = *(const float2*)(p0 + 4096);
        }
        uint32_t rowb = sb + SM_RING + (uint32_t)(((rg + 5) % 5) * 64) * 128;
        uint32_t d0 = rowb + (uint32_t)j0 * 128
                    + (((uint32_t)icp << 2) ^ (((uint32_t)j0 & 7) << 4));
        uint32_t d1 = rowb + (uint32_t)(j0 + 1) * 128
                    + (((uint32_t)icp << 2) ^ (((uint32_t)(j0 + 1) & 7) << 4));
        sts32(d0, f2h2(a0.x, a1.x));
        sts32(d1, f2h2(a0.y, a1.y));
    }
}

__global__ __launch_bounds__(NT, 1)
void convt_mma_kernel(const float* __restrict__ x,
                      const float* __restrict__ weight,
                      const float* __restrict__ bias,
                      float* __restrict__ out) {
    extern __shared__ char smem[];
    const uint32_t sb = s2u(smem);
    const int tid  = threadIdx.x;
    const int warp = tid >> 5;
    const int lane = tid & 31;
    const int ph   = blockIdx.x & 1;
    const int slot = blockIdx.x >> 1;      // 0..73

    if (tid < 64) ((float*)smem)[tid] = bias[tid];

    // ---- stage B once (fp16): row = pw*64+oc (512B), word kp: byte = kp*4 ^ ((oc&7)<<4) ----
    for (int it = 0; it < 32; it++) {
        int idx = tid + it * NT;           // 0..16383 (k-pairs)
        int kp = idx & 127;                // k0 = 2*kp
        int oc = (idx >> 7) & 63;
        int pw = idx >> 13;
        int k0 = 2 * kp;
        int g = k0 >> 6, ic = k0 & 63, a = g & 1, b = g >> 1;
        int kh = (1 - ph) + 2 * a;
        int kw = (1 - pw) + 2 * b;
        const float* wp = weight + ((oc * 64 + ic) << 4) + (kh << 2) + kw;
        float f0 = __ldg(wp);
        float f1 = __ldg(wp + 16);         // ic+1, same (kh,kw)
        uint32_t byte = ((uint32_t)(kp << 2)) ^ ((uint32_t)(oc & 7) << 4);
        sts32(sb + SM_B + (pw * 64 + oc) * 512 + byte, f2h2(f0, f1));
    }
    if (tid < 32) sts32(sb + SM_RING + ZROW * 128 + tid * 4, 0u);   // zero row

    // warp roles: pw | och | mq
    const int pw  = warp >> 3;
    const int och = (warp >> 2) & 1;
    const int mq  = warp & 3;
    const int p0  = 32 * mq;
    const int ohi = mq >> 1;
    const int msub0 = 32 * (mq & 1);

    const int l15 = lane & 15;
    const int lhi = lane >> 4;
    const int oc_l = (lane & 7) + 8 * lhi;
    const uint32_t khalf = (uint32_t)((lane >> 3) & 1) << 4;
    const uint32_t swzB  = (uint32_t)(lane & 7) << 4;
    uint32_t rbB[2];
#pragma unroll
    for (int jp = 0; jp < 2; jp++)
        rbB[jp] = sb + SM_B + (uint32_t)(pw * 64 + 32 * och + 16 * jp + oc_l) * 512;

    const int gL = lane >> 2, tg = lane & 3;
    const float* bsm = (const float*)smem;

    for (int u = slot; u < 512; u += 74) {
        const int n  = u >> 3;
        const int uh = u & 7;
        const int Rb0 = 8 * uh + ph;
        const float* xn = x + (size_t)n * (64 * 64 * 64);

        // ---- prologue: rows Rb0-1..Rb0+1 ----
        stage_rows(xn, Rb0 - 1, 3, sb, tid);
        __syncthreads();

        for (int tl = 0; tl < 4; tl++) {
            const int Rb = Rb0 + 2 * tl;
            const int tglob = 4 * uh + tl;

            // ---- phase A: stage rows Rb+2, Rb+3 (next tile) ----
            if (tl < 3) stage_rows(xn, Rb + 2, 2, sb, tid);

            // ---- phase B: mma from slots (Rb-1, Rb, Rb+1), 16 k16-steps ----
            float acc[2][4][4];
#pragma unroll
            for (int i = 0; i < 2; i++)
#pragma unroll
                for (int j = 0; j < 4; j++)
#pragma unroll
                    for (int e = 0; e < 4; e++) acc[i][j][e] = 0.0f;

#pragma unroll
            for (int g = 0; g < 4; g++) {
                const int a = g & 1, b = g >> 1;
                const int rgA = Rb + ohi - a;
                const int slotA = (rgA + 5) % 5;
                const int jA = msub0 + pw - b + l15;
                const int rowL0 = ((unsigned)jA < 64u) ? slotA * 64 + jA : ZROW;
                const int rowL1 = ((unsigned)(jA + 16) < 64u) ? slotA * 64 + jA + 16 : ZROW;
                const uint32_t base0 = sb + SM_RING + (uint32_t)rowL0 * 128;
                const uint32_t base1 = sb + SM_RING + (uint32_t)rowL1 * 128;
                const uint32_t r0 = (uint32_t)(rowL0 & 7);
                const uint32_t r1 = (uint32_t)(rowL1 & 7);
                const uint32_t kbg = (uint32_t)g << 7;   // g*128 bytes

#pragma unroll
                for (int s = 0; s < 4; s++) {
                    const uint32_t ch = (uint32_t)(s << 1) + (uint32_t)lhi;  // 0..7
                    uint32_t Af0[4], Af1[4];
                    ldsm4(Af0, base0 + ((ch ^ r0) << 4));
                    ldsm4(Af1, base1 + ((ch ^ r1) << 4));
                    const uint32_t kb = (kbg + ((uint32_t)s << 5) + khalf) ^ swzB;
                    uint32_t Bf0[4], Bf1[4];
                    ldsm4(Bf0, rbB[0] + kb);
                    ldsm4(Bf1, rbB[1] + kb);
                    mma16(acc[0][0], Af0, Bf0[0], Bf0[1]);
                    mma16(acc[0][1], Af0, Bf0[2], Bf0[3]);
                    mma16(acc[0][2], Af0, Bf1[0], Bf1[1]);
                    mma16(acc[0][3], Af0, Bf1[2], Bf1[3]);
                    mma16(acc[1][0], Af1, Bf0[0], Bf0[1]);
                    mma16(acc[1][1], Af1, Bf0[2], Bf0[3]);
                    mma16(acc[1][2], Af1, Bf1[0], Bf1[1]);
                    mma16(acc[1][3], Af1, Bf1[2], Bf1[3]);
                }
            }
            __syncthreads();   // sync1: ring reads done; phase-A STS visible next tile

            // ---- phase C: ys 2x32KB double buffer, 2 chunks x 32oc, 3 barriers ----
            const uint32_t ysA = sb + SM_YS;
            const uint32_t ysB = sb + SM_YS + 32768;

#define WRITE_CHUNK(q, base) do {                                            \
    _Pragma("unroll")                                                        \
    for (int jj_ = 0; jj_ < 2; jj_++) {                                      \
        const int j_  = 2 * (q) + jj_;                                       \
        const int oc_ = 32 * och + 8 * j_ + 2 * tg;                          \
        const int row_ = pw * 32 + och * 16 + 8 * jj_ + 2 * tg;              \
        const float b0v_ = bsm[oc_], b1v_ = bsm[oc_ + 1];                    \
        _Pragma("unroll")                                                    \
        for (int i_ = 0; i_ < 2; i_++) {                                     \
            const int pr_ = p0 + 16 * i_ + gL;                               \
            sts32(ysaddr((base), row_,     pr_),     __float_as_uint(postop(acc[i_][j_][0] + b0v_))); \
            sts32(ysaddr((base), row_ + 1, pr_),     __float_as_uint(postop(acc[i_][j_][1] + b1v_))); \
            sts32(ysaddr((base), row_,     pr_ + 8), __float_as_uint(postop(acc[i_][j_][2] + b0v_))); \
            sts32(ysaddr((base), row_ + 1, pr_ + 8), __float_as_uint(postop(acc[i_][j_][3] + b1v_))); \
        }                                                                    \
    } } while (0)

#define STORE_CHUNK(q, base) do {                                            \
    const char* yb_ = smem + ((base) - sb);                                  \
    _Pragma("unroll")                                                        \
    for (int it_ = 0; it_ < 4; it_++) {                                      \
        int vid_ = tid + it_ * NT;     /* 0..2047 */                         \
        int ow4_ = vid_ & 31;                                                \
        int rw_  = vid_ >> 5;          /* 0..63 */                           \
        int oh2_ = rw_ & 1;                                                  \
        int ocy_ = rw_ >> 1;           /* 0..31 */                           \
        int oc_  = 32 * (ocy_ >> 4) + 16 * (q) + (ocy_ & 15);                \
        int p_   = oh2_ * 64 + 2 * ow4_;                                     \
        float4 v_;                                                           \
        v_.x = *(const float*)(yb_ + (ysaddr(0u, ocy_,      p_)));           \
        v_.y = *(const float*)(yb_ + (ysaddr(0u, 32 + ocy_, p_)));           \
        v_.z = *(const float*)(yb_ + (ysaddr(0u, ocy_,      p_ + 1)));       \
        v_.w = *(const float*)(yb_ + (ysaddr(0u, 32 + ocy_, p_ + 1)));       \
        int oh_ = ph + 4 * tglob + 2 * oh2_;                                 \
        *(float4*)(out + (((size_t)n * 64 + oc_) * 128 + oh_) * 128 + 4 * ow4_) = v_; \
    } } while (0)

            WRITE_CHUNK(0, ysA);
            __syncthreads();               // sync2
            STORE_CHUNK(0, ysA); WRITE_CHUNK(1, ysB);
            __syncthreads();               // sync3
            STORE_CHUNK(1, ysB);
            // no final sync: next tile's sync1/sync2 order all cross-warp hazards
#undef WRITE_CHUNK
#undef STORE_CHUNK
        }
    }
}

extern "C" void kernel_launch(void* const* d_in, const int* in_sizes, int n_in,
                              void* d_out, int out_size) {
    const float* x      = (const float*)d_in[0];
    const float* weight = (const float*)d_in[1];
    const float* bias   = (const float*)d_in[2];
    float* out          = (float*)d_out;

    cudaFuncSetAttribute(convt_mma_kernel,
                         cudaFuncAttributeMaxDynamicSharedMemorySize, SMEM_TOTAL);
    convt_mma_kernel<<<148, NT, SMEM_TOTAL>>>(x, weight, bias, out);
}

// round 14
// speedup vs baseline: 1.0584x; 1.0038x over previous
#include <cuda_runtime.h>
#include <cstdint>

// ConvTranspose2d(64->64,k4,s2,p1)+bias+mish+(+0.5,clip,*2) via mma.sync fp16 (f32 accum).
// y[p,oc] = sum_k A[p,k]*B[oc,k], k = (b*2+a)*64 + ic, K=256.
//   pixel p=(ohi,m): oh = ph+4*tglob+2*ohi, ow = 2m+pw ; Rb = 2*tglob+ph
//   A[p,k] = x[n, ic, Rb+ohi-a, m+pw-b]  (zero OOB), B[oc,k]=w[oc,ic,(1-ph)+2a,(1-pw)+2b]
// Round-11 structure (best: 192.5us) with the SMEM epilogue REPLACED by direct
// scattered STG.32 from accumulators: each warp owns one oh row; per-warp stores
// touch 8 sectors/instr whose complementary halves come from the pw-partner warp
// (same CTA, same time) -> L2 merges before DRAM. ys buffer deleted; barriers
// drop from 6 to 1 per tile (only the ring producer/consumer sync remains).
// 5-slot fp16 row ring (row=slot*64+j, 128B = 64 ic, 16B-chunk swizzle ^(j&7)<<4,
// OOB j -> ZROW). Staging: LDG.32 ic-pair -> cvt.rn.f16x2 -> STS.32.
// Work unit = 4 tiles (512 units/ph, 74 slots). Grid 148, 512 thr,
// 16 warps = (pw, och, mq), warp tile 32px x 32oc, 16 k16-steps.

#define NT 512
#define SM_B    256
#define SM_RING (SM_B + 65536)             // 65792
#define ZROW    320
#define SMEM_TOTAL (SM_RING + 321 * 128)   // 106880

static __device__ __forceinline__ uint32_t s2u(const void* p) {
    uint32_t a;
    asm("{ .reg .u64 t; cvta.to.shared.u64 t, %1; cvt.u32.u64 %0, t; }" : "=r"(a) : "l"(p));
    return a;
}
static __device__ __forceinline__ uint32_t f2h2(float lo, float hi) {
    uint32_t r;
    asm("cvt.rn.f16x2.f32 %0, %1, %2;" : "=r"(r) : "f"(hi), "f"(lo));
    return r;
}
static __device__ __forceinline__ void sts32(uint32_t addr, uint32_t v) {
    asm volatile("st.shared.b32 [%0], %1;" :: "r"(addr), "r"(v) : "memory");
}
static __device__ __forceinline__ void ldsm4(uint32_t* r, uint32_t addr) {
    asm volatile("ldmatrix.sync.aligned.m8n8.x4.shared.b16 {%0,%1,%2,%3}, [%4];"
                 : "=r"(r[0]), "=r"(r[1]), "=r"(r[2]), "=r"(r[3]) : "r"(addr));
}
static __device__ __forceinline__ void mma16(float* d, const uint32_t* a,
                                             uint32_t b0, uint32_t b1) {
    asm volatile("mma.sync.aligned.m16n8k16.row.col.f32.f16.f16.f32 "
                 "{%0,%1,%2,%3}, {%4,%5,%6,%7}, {%8,%9}, {%0,%1,%2,%3};"
                 : "+f"(d[0]), "+f"(d[1]), "+f"(d[2]), "+f"(d[3])
                 : "r"(a[0]), "r"(a[1]), "r"(a[2]), "r"(a[3]), "r"(b0), "r"(b1));
}
__device__ __forceinline__ float postop(float y) {
    // mish(y) = y*(t^2+2t)/(t^2+2t+2), t=e^y ; then +0.5, clip[-1,1], *2
    float t = __expf(fminf(y, 30.0f));
    float u = t * (t + 2.0f);
    float mish = y * __fdividef(u, u + 2.0f);
    float v = fminf(fmaxf(mish + 0.5f, -1.0f), 1.0f);
    return v * 2.0f;
}

// stage nrows rows starting at rg0: LDG.32 ic-pair -> f16x2 -> STS.32
static __device__ __forceinline__ void stage_rows(const float* xn, int rg0, int nrows,
                                                  uint32_t sb, int tid) {
    const int total = nrows * 2048;        // pairs: 32 icp x 64 j per row
#pragma unroll 4
    for (int idx = tid; idx < total; idx += NT) {
        int j   = idx & 63;
        int icp = (idx >> 6) & 31;
        int rr  = idx >> 11;
        int rg  = rg0 + rr;
        float v0 = 0.0f, v1 = 0.0f;
        if ((unsigned)rg < 64u) {
            const float* p0 = xn + ((2 * icp) * 64 + rg) * 64 + j;
            v0 = __ldg(p0);
            v1 = __ldg(p0 + 4096);
        }
        int row = ((rg + 5) % 5) * 64 + j;
        uint32_t dst = sb + SM_RING + row * 128
                     + (((uint32_t)icp << 2) ^ (((uint32_t)j & 7) << 4));
        sts32(dst, f2h2(v0, v1));
    }
}

__global__ __launch_bounds__(NT, 1)
void convt_mma_kernel(const float* __restrict__ x,
                      const float* __restrict__ weight,
                      const float* __restrict__ bias,
                      float* __restrict__ out) {
    extern __shared__ char smem[];
    const uint32_t sb = s2u(smem);
    const int tid  = threadIdx.x;
    const int warp = tid >> 5;
    const int lane = tid & 31;
    const int ph   = blockIdx.x & 1;
    const int slot = blockIdx.x >> 1;      // 0..73

    if (tid < 64) ((float*)smem)[tid] = bias[tid];

    // ---- stage B once (fp16): row = pw*64+oc (512B), word kp: byte = kp*4 ^ ((oc&7)<<4) ----
    for (int it = 0; it < 32; it++) {
        int idx = tid + it * NT;           // 0..16383 (k-pairs)
        int kp = idx & 127;                // k0 = 2*kp
        int oc = (idx >> 7) & 63;
        int pw = idx >> 13;
        int k0 = 2 * kp;
        int g = k0 >> 6, ic = k0 & 63, a = g & 1, b = g >> 1;
        int kh = (1 - ph) + 2 * a;
        int kw = (1 - pw) + 2 * b;
        const float* wp = weight + ((oc * 64 + ic) << 4) + (kh << 2) + kw;
        float f0 = __ldg(wp);
        float f1 = __ldg(wp + 16);         // ic+1, same (kh,kw)
        uint32_t byte = ((uint32_t)(kp << 2)) ^ ((uint32_t)(oc & 7) << 4);
        sts32(sb + SM_B + (pw * 64 + oc) * 512 + byte, f2h2(f0, f1));
    }
    if (tid < 32) sts32(sb + SM_RING + ZROW * 128 + tid * 4, 0u);   // zero row

    // warp roles: pw | och | mq
    const int pw  = warp >> 3;
    const int och = (warp >> 2) & 1;
    const int mq  = warp & 3;
    const int p0  = 32 * mq;
    const int ohi = mq >> 1;
    const int msub0 = 32 * (mq & 1);

    const int l15 = lane & 15;
    const int lhi = lane >> 4;
    const int oc_l = (lane & 7) + 8 * lhi;
    const uint32_t khalf = (uint32_t)((lane >> 3) & 1) << 4;
    const uint32_t swzB  = (uint32_t)(lane & 7) << 4;
    uint32_t rbB[2];
#pragma unroll
    for (int jp = 0; jp < 2; jp++)
        rbB[jp] = sb + SM_B + (uint32_t)(pw * 64 + 32 * och + 16 * jp + oc_l) * 512;

    const int gL = lane >> 2, tg = lane & 3;
    const float* bsm = (const float*)smem;

    for (int u = slot; u < 512; u += 74) {
        const int n  = u >> 3;
        const int uh = u & 7;
        const int Rb0 = 8 * uh + ph;
        const float* xn = x + (size_t)n * (64 * 64 * 64);

        // ---- prologue: rows Rb0-1..Rb0+1 ----
        stage_rows(xn, Rb0 - 1, 3, sb, tid);
        __syncthreads();

        for (int tl = 0; tl < 4; tl++) {
            const int Rb = Rb0 + 2 * tl;
            const int tglob = 4 * uh + tl;

            // ---- phase A: stage rows Rb+2, Rb+3 (next tile) ----
            if (tl < 3) stage_rows(xn, Rb + 2, 2, sb, tid);

            // ---- phase B: mma from slots (Rb-1, Rb, Rb+1), 16 k16-steps ----
            float acc[2][4][4];
#pragma unroll
            for (int i = 0; i < 2; i++)
#pragma unroll
                for (int j = 0; j < 4; j++)
#pragma unroll
                    for (int e = 0; e < 4; e++) acc[i][j][e] = 0.0f;

#pragma unroll
            for (int g = 0; g < 4; g++) {
                const int a = g & 1, b = g >> 1;
                const int rgA = Rb + ohi - a;
                const int slotA = (rgA + 5) % 5;
                const int jA = msub0 + pw - b + l15;
                const int rowL0 = ((unsigned)jA < 64u) ? slotA * 64 + jA : ZROW;
                const int rowL1 = ((unsigned)(jA + 16) < 64u) ? slotA * 64 + jA + 16 : ZROW;
                const uint32_t base0 = sb + SM_RING + (uint32_t)rowL0 * 128;
                const uint32_t base1 = sb + SM_RING + (uint32_t)rowL1 * 128;
                const uint32_t r0 = (uint32_t)(rowL0 & 7);
                const uint32_t r1 = (uint32_t)(rowL1 & 7);
                const uint32_t kbg = (uint32_t)g << 7;   // g*128 bytes

#pragma unroll
                for (int s = 0; s < 4; s++) {
                    const uint32_t ch = (uint32_t)(s << 1) + (uint32_t)lhi;  // 0..7
                    uint32_t Af0[4], Af1[4];
                    ldsm4(Af0, base0 + ((ch ^ r0) << 4));
                    ldsm4(Af1, base1 + ((ch ^ r1) << 4));
                    const uint32_t kb = (kbg + ((uint32_t)s << 5) + khalf) ^ swzB;
                    uint32_t Bf0[4], Bf1[4];
                    ldsm4(Bf0, rbB[0] + kb);
                    ldsm4(Bf1, rbB[1] + kb);
                    mma16(acc[0][0], Af0, Bf0[0], Bf0[1]);
                    mma16(acc[0][1], Af0, Bf0[2], Bf0[3]);
                    mma16(acc[0][2], Af0, Bf1[0], Bf1[1]);
                    mma16(acc[0][3], Af0, Bf1[2], Bf1[3]);
                    mma16(acc[1][0], Af1, Bf0[0], Bf0[1]);
                    mma16(acc[1][1], Af1, Bf0[2], Bf0[3]);
                    mma16(acc[1][2], Af1, Bf1[0], Bf1[1]);
                    mma16(acc[1][3], Af1, Bf1[2], Bf1[3]);
                }
            }
            __syncthreads();   // sync1: ring reads done; phase-A STS visible next tile

            // ---- phase C: postop + direct STG from accumulators (no smem, no syncs)
            //      thread outputs: p = p0+16i+gL (+8), oc = 32och+8j+2tg (+1)
            //      oh = ph+4tglob+2ohi (constant per warp), ow = 2m+pw, m = p&63
            {
                const int oh = ph + 4 * tglob + 2 * ohi;
                float* ob = out + (size_t)n * (64 * 16384) + (size_t)oh * 128 + pw;
#pragma unroll
                for (int i = 0; i < 2; i++) {
                    const int m0 = (p0 + 16 * i + gL) & 63;
                    float* orow = ob + 2 * m0;
#pragma unroll
                    for (int j = 0; j < 4; j++) {
                        const int oc = 32 * och + 8 * j + 2 * tg;
                        const float b0v = bsm[oc], b1v = bsm[oc + 1];
                        float* o0 = orow + (size_t)oc * 16384;
                        o0[0]         = postop(acc[i][j][0] + b0v);
                        o0[16384]     = postop(acc[i][j][1] + b1v);
                        o0[16]        = postop(acc[i][j][2] + b0v);   // m+8 -> ow+16
                        o0[16384 + 16] = postop(acc[i][j][3] + b1v);
                    }
                }
            }
            // no epilogue barriers: STG targets gmem only; next tile's phase A
            // (ring STS) was ordered by sync1 above.
        }
    }
}

extern "C" void kernel_launch(void* const* d_in, const int* in_sizes, int n_in,
                              void* d_out, int out_size) {
    const float* x      = (const float*)d_in[0];
    const float* weight = (const float*)d_in[1];
    const float* bias   = (const float*)d_in[2];
    float* out          = (float*)d_out;

    cudaFuncSetAttribute(convt_mma_kernel,
                         cudaFuncAttributeMaxDynamicSharedMemorySize, SMEM_TOTAL);
    convt_mma_kernel<<<148, NT, SMEM_TOTAL>>>(x, weight, bias, out);
}